// round 16
// baseline (speedup 1.0000x reference)
#include <cuda_runtime.h>
#include <cuda_bf16.h>
#include <cuda_fp8.h>
#include <math.h>

#define C_DIM 1000
#define ALPHA 0.01f
#define EPS_V 1e-15f
#define WARPS_PER_BLOCK 8
#define LOSS_BLOCKS 592           // 148 SMs x 4 blocks (persistent grid)
#define TOTAL_WARPS (LOSS_BLOCKS * WARPS_PER_BLOCK)
#define N_TILES 1024
#define MAX_PARTIALS 16384
#define TT_SCALE 128.0f
#define TT_INV_SCALE 0.0078125f   // 1/128

// Scratch (zero-initialized at module load).
__device__ unsigned int g_Tt8[C_DIM * C_DIM / 4];   // fp8 e4m3 Tt (x128), 1 MB
__device__ float g_partials[MAX_PARTIALS];
__device__ int   g_tile_ctr;     // work-stealing counter (reset by reduce)
__device__ int   g_tiles_done;   // completed-tile count (reset by reduce)

// fp8x2 (e4m3) -> float2
__device__ __forceinline__ float2 f8x2_to_f2(unsigned int v) {
    __half2_raw hr = __nv_cvt_fp8x2_to_halfraw2((__nv_fp8x2_storage_t)v, __NV_E4M3);
    return __half22float2(*reinterpret_cast<__half2*>(&hr));
}

// ---------------------------------------------------------------------------
// Fused persistent kernel.
// Phase A: blocks work-steal 32x32 transpose tiles of Tt8 (any resident
//          subset completes all tiles -> deadlock-free).
// Phase B: wait for all tiles (zero live registers), then R15 loss loop:
//          one warp per row per iteration, grid-stride.
// ---------------------------------------------------------------------------
__global__ __launch_bounds__(256) void fused_kernel(
    const float* __restrict__ logits,
    const int* __restrict__ target,
    const float* __restrict__ T,
    const float* __restrict__ corr,
    int B) {
    const int tid = threadIdx.x;

    __shared__ int   s_tile;
    __shared__ float tile[32][34];
    __shared__ float wsum[WARPS_PER_BLOCK];

    // ================= Phase A: work-steal transpose tiles =================
    for (;;) {
        if (tid == 0) s_tile = atomicAdd(&g_tile_ctr, 1);
        __syncthreads();
        const int tileIdx = s_tile;
        if (tileIdx >= N_TILES) break;

        const int t0 = (tileIdx & 31) * 32;
        const int c0 = (tileIdx >> 5) * 32;

        // load: thread (c_local = tid>>3, f4 = tid&7) loads one float4 pair
        const int c_local = tid >> 3;
        const int c = c0 + c_local;
        const int f4 = (t0 >> 2) + (tid & 7);
        if (c < C_DIM && f4 < C_DIM / 4) {
            float4 a = __ldg(&reinterpret_cast<const float4*>(T    + (size_t)c * C_DIM)[f4]);
            float4 b = __ldg(&reinterpret_cast<const float4*>(corr + (size_t)c * C_DIM)[f4]);
            const int tl = (tid & 7) * 4;
            tile[tl + 0][c_local] = a.x + ALPHA * b.x;
            tile[tl + 1][c_local] = a.y + ALPHA * b.y;
            tile[tl + 2][c_local] = a.z + ALPHA * b.z;
            tile[tl + 3][c_local] = a.w + ALPHA * b.w;
        }
        __syncthreads();

        // store: thread handles t-row tl = tid>>3, 4 consecutive c (packed fp8)
        {
            const int tl = tid >> 3;
            const int c4 = tid & 7;
            const int t  = t0 + tl;
            const int cc = c0 + 4 * c4;
            if (t < C_DIM && cc < C_DIM) {
                unsigned int b0 = __nv_cvt_float_to_fp8(tile[tl][4 * c4 + 0] * TT_SCALE, __NV_SATFINITE, __NV_E4M3);
                unsigned int b1 = __nv_cvt_float_to_fp8(tile[tl][4 * c4 + 1] * TT_SCALE, __NV_SATFINITE, __NV_E4M3);
                unsigned int b2 = __nv_cvt_float_to_fp8(tile[tl][4 * c4 + 2] * TT_SCALE, __NV_SATFINITE, __NV_E4M3);
                unsigned int b3 = __nv_cvt_float_to_fp8(tile[tl][4 * c4 + 3] * TT_SCALE, __NV_SATFINITE, __NV_E4M3);
                g_Tt8[(size_t)t * (C_DIM / 4) + (cc >> 2)] = b0 | (b1 << 8) | (b2 << 16) | (b3 << 24);
            }
        }
        __syncthreads();   // stores done + protects tile/s_tile reuse
        if (tid == 0) {
            __threadfence();                 // release tile stores
            atomicAdd(&g_tiles_done, 1);
        }
    }

    // ================= wait: all tiles complete (no live state) ============
    if (tid == 0) {
        while (*((volatile int*)&g_tiles_done) < N_TILES) __nanosleep(64);
    }
    __syncthreads();
    __threadfence();       // acquire: order Tt8 reads after flag observation

    // ================= Phase B: persistent loss loop (R15 body) ============
    const int warp  = tid >> 5;
    const int lane  = tid & 31;
    const int gwarp = blockIdx.x * WARPS_PER_BLOCK + warp;

    float acc = 0.0f;

    for (int row = gwarp; row < B; row += TOTAL_WARPS) {
        const float4* r4 = reinterpret_cast<const float4*>(logits + (size_t)row * C_DIM);
        int t = target[row];
        t = (t < 0) ? 0 : ((t >= C_DIM) ? C_DIM - 1 : t);
        const uint2* tt8 = reinterpret_cast<const uint2*>(g_Tt8 + (size_t)t * (C_DIM / 4));

        float4 v[8];
        uint2  q[4];
#pragma unroll
        for (int j = 0; j < 4; j++) {
            const int i4 = lane + 32 * j;
            if (i4 < 125) {
                v[2 * j]     = __ldcs(&r4[2 * i4]);
                v[2 * j + 1] = __ldcs(&r4[2 * i4 + 1]);
                q[j]         = __ldg(&tt8[i4]);
            } else {
                v[2 * j]     = make_float4(-INFINITY, -INFINITY, -INFINITY, -INFINITY);
                v[2 * j + 1] = make_float4(-INFINITY, -INFINITY, -INFINITY, -INFINITY);
                q[j]         = make_uint2(0u, 0u);   // e4m3 0x00 == 0.0
            }
        }

        // ---- extract x_t (uniform shuffle) from raw logits ----
        const int f    = t >> 2;
        const int i4t  = f >> 1;
        const int reg  = ((i4t >> 5) << 1) | (f & 1);
        const int srcl = i4t & 31;
        const int comp = t & 3;
        float4 vt;
        switch (reg) {
            case 0: vt = v[0]; break; case 1: vt = v[1]; break;
            case 2: vt = v[2]; break; case 3: vt = v[3]; break;
            case 4: vt = v[4]; break; case 5: vt = v[5]; break;
            case 6: vt = v[6]; break; default: vt = v[7]; break;
        }
        float cand = (comp == 0) ? vt.x : (comp == 1) ? vt.y : (comp == 2) ? vt.z : vt.w;
        const float x_t = __shfl_sync(0xffffffffu, cand, srcl);

        // ---- exp + sum + dot (fp8 decode) ----
        float s = 0.0f, d = 0.0f;
#pragma unroll
        for (int j = 0; j < 4; j++) {
            float4 a = v[2 * j];
            float4 b = v[2 * j + 1];
            a.x = __expf(a.x); a.y = __expf(a.y); a.z = __expf(a.z); a.w = __expf(a.w);
            b.x = __expf(b.x); b.y = __expf(b.y); b.z = __expf(b.z); b.w = __expf(b.w);
            s += (a.x + a.y + a.z + a.w) + (b.x + b.y + b.z + b.w);
            float2 p0 = f8x2_to_f2(q[j].x & 0xFFFFu);
            float2 p1 = f8x2_to_f2(q[j].x >> 16);
            float2 p2 = f8x2_to_f2(q[j].y & 0xFFFFu);
            float2 p3 = f8x2_to_f2(q[j].y >> 16);
            d += a.x * p0.x + a.y * p0.y + a.z * p1.x + a.w * p1.y
               + b.x * p2.x + b.y * p2.y + b.z * p3.x + b.w * p3.y;
        }

#pragma unroll
        for (int o = 16; o > 0; o >>= 1) {
            s += __shfl_xor_sync(0xffffffffu, s, o);
            d += __shfl_xor_sync(0xffffffffu, d, o);
        }

        if (lane == 0) {
            float lse  = __logf(s);
            float ce   = lse - x_t;                       // -log_softmax[t]
            float pro1 = __expf(x_t) / s;                 // p[t]
            float pro2 = (d * TT_INV_SCALE) / s;          // dot(p, Tt[t])
            float beta = pro1 / (pro2 + EPS_V);
            acc += beta * ce;
        }
    }

    if (lane == 0) wsum[warp] = acc;
    __syncthreads();

    if (tid == 0) {
        float s = 0.0f;
#pragma unroll
        for (int w = 0; w < WARPS_PER_BLOCK; w++) s += wsum[w];
        g_partials[blockIdx.x] = s;
    }
}

// ---------------------------------------------------------------------------
// Final reduction (deterministic) + counter reset for next graph replay.
// ---------------------------------------------------------------------------
__global__ __launch_bounds__(1024) void final_reduce_kernel(float* __restrict__ out,
                                                            float invB) {
    __shared__ float sh[1024];
    const int tid = threadIdx.x;
    float acc[MAX_PARTIALS / 1024];
#pragma unroll
    for (int k = 0; k < MAX_PARTIALS / 1024; k++)
        acc[k] = g_partials[tid + 1024 * k];
    float s = 0.0f;
#pragma unroll
    for (int k = 0; k < MAX_PARTIALS / 1024; k++) s += acc[k];
    sh[tid] = s;
    __syncthreads();
#pragma unroll
    for (int o = 512; o > 0; o >>= 1) {
        if (tid < o) sh[tid] += sh[tid + o];
        __syncthreads();
    }
    if (tid == 0) {
        out[0] = sh[0] * invB;
        g_tile_ctr   = 0;          // reset for next graph replay
        g_tiles_done = 0;
    }
}

// ---------------------------------------------------------------------------
extern "C" void kernel_launch(void* const* d_in, const int* in_sizes, int n_in,
                              void* d_out, int out_size) {
    const float* logits = (const float*)d_in[0];   // [B, C] fp32
    const float* corr   = (const float*)d_in[1];   // [C, C] fp32
    const int*   target = (const int*)d_in[2];     // [B] int32
    const float* T      = (const float*)d_in[3];   // [C, C] fp32

    const int B = in_sizes[2];

    fused_kernel<<<LOSS_BLOCKS, 32 * WARPS_PER_BLOCK>>>(logits, target, T, corr, B);
    final_reduce_kernel<<<1, 1024>>>((float*)d_out, 1.0f / (float)B);
}

// round 17
// speedup vs baseline: 1.0417x; 1.0417x over previous
#include <cuda_runtime.h>
#include <cuda_bf16.h>
#include <cuda_fp8.h>
#include <math.h>

#define C_DIM 1000
#define ALPHA 0.01f
#define EPS_V 1e-15f
#define WARPS_PER_BLOCK 8
#define LOSS_BLOCKS 592           // 148 SMs x 4 blocks (persistent grid)
#define TOTAL_WARPS (LOSS_BLOCKS * WARPS_PER_BLOCK)
#define MAX_PARTIALS 16384
#define TT_SCALE 128.0f
#define TT_INV_SCALE 0.0078125f   // 1/128

// Scratch: transposed T_result in fp8 e4m3 (x128), packed 4/word.
__device__ unsigned int g_Tt8[C_DIM * C_DIM / 4];   // 1 MB
__device__ float g_partials[MAX_PARTIALS];

// ---------------------------------------------------------------------------
// Kernel 1: prep with CONTIGUOUS reads. Block b owns c-rows [4b, 4b+4):
// reads 2 x 16 KB sequential runs, converts to fp8 in-register, stages
// packed words in smem, then 4x4-byte PRMT transpose -> g_Tt8[t][c] words.
// ---------------------------------------------------------------------------
__global__ __launch_bounds__(256) void prep_T_kernel(const float* __restrict__ T,
                                                     const float* __restrict__ corr) {
    __shared__ unsigned int sm[4][256];   // [c_local][t_group], 250 used
    const int c0  = blockIdx.x * 4;
    const int tid = threadIdx.x;

    const float4* Tb = reinterpret_cast<const float4*>(T    + (size_t)c0 * C_DIM);
    const float4* Cb = reinterpret_cast<const float4*>(corr + (size_t)c0 * C_DIM);

#pragma unroll
    for (int k = 0; k < 4; k++) {
        const int i = tid + 256 * k;            // float4 index within 4 rows (0..999)
        if (i < 1000) {
            float4 a = __ldg(&Tb[i]);
            float4 b = __ldg(&Cb[i]);
            unsigned int b0 = __nv_cvt_float_to_fp8((a.x + ALPHA * b.x) * TT_SCALE, __NV_SATFINITE, __NV_E4M3);
            unsigned int b1 = __nv_cvt_float_to_fp8((a.y + ALPHA * b.y) * TT_SCALE, __NV_SATFINITE, __NV_E4M3);
            unsigned int b2 = __nv_cvt_float_to_fp8((a.z + ALPHA * b.z) * TT_SCALE, __NV_SATFINITE, __NV_E4M3);
            unsigned int b3 = __nv_cvt_float_to_fp8((a.w + ALPHA * b.w) * TT_SCALE, __NV_SATFINITE, __NV_E4M3);
            const int c_local = i / 250;        // 0..3
            const int g       = i % 250;        // t-group (t = 4g..4g+3)
            sm[c_local][g] = b0 | (b1 << 8) | (b2 << 16) | (b3 << 24);
        }
    }
    __syncthreads();

    // transpose: thread g emits output words for t = 4g..4g+3
    if (tid < 250) {
        const unsigned int w0 = sm[0][tid];
        const unsigned int w1 = sm[1][tid];
        const unsigned int w2 = sm[2][tid];
        const unsigned int w3 = sm[3][tid];
#pragma unroll
        for (int j = 0; j < 4; j++) {
            const unsigned int sel = (unsigned)j | ((unsigned)(j + 4) << 4);
            unsigned int lo  = __byte_perm(w0, w1, sel);       // {w0[j], w1[j]}
            unsigned int hi  = __byte_perm(w2, w3, sel);       // {w2[j], w3[j]}
            unsigned int out = __byte_perm(lo, hi, 0x5410);    // {w0[j],w1[j],w2[j],w3[j]}
            g_Tt8[(size_t)(4 * tid + j) * (C_DIM / 4) + blockIdx.x] = out;
        }
    }
}

// fp8x2 (e4m3) -> float2
__device__ __forceinline__ float2 f8x2_to_f2(unsigned int v) {
    __half2_raw hr = __nv_cvt_fp8x2_to_halfraw2((__nv_fp8x2_storage_t)v, __NV_E4M3);
    return __half22float2(*reinterpret_cast<__half2*>(&hr));
}

// ---------------------------------------------------------------------------
// Kernel 2: PERSISTENT grid, one warp per row per iteration (R15 verbatim).
// ---------------------------------------------------------------------------
__global__ __launch_bounds__(256) void row_loss_kernel(
    const float* __restrict__ logits,
    const int* __restrict__ target,
    int B) {
    const int warp  = threadIdx.x >> 5;
    const int lane  = threadIdx.x & 31;
    const int gwarp = blockIdx.x * WARPS_PER_BLOCK + warp;

    __shared__ float wsum[WARPS_PER_BLOCK];
    float acc = 0.0f;

    for (int row = gwarp; row < B; row += TOTAL_WARPS) {
        const float4* r4 = reinterpret_cast<const float4*>(logits + (size_t)row * C_DIM);
        int t = target[row];
        t = (t < 0) ? 0 : ((t >= C_DIM) ? C_DIM - 1 : t);
        const uint2* tt8 = reinterpret_cast<const uint2*>(g_Tt8 + (size_t)t * (C_DIM / 4));

        float4 v[8];
        uint2  q[4];
#pragma unroll
        for (int j = 0; j < 4; j++) {
            const int i4 = lane + 32 * j;
            if (i4 < 125) {
                v[2 * j]     = __ldcs(&r4[2 * i4]);
                v[2 * j + 1] = __ldcs(&r4[2 * i4 + 1]);
                q[j]         = __ldg(&tt8[i4]);
            } else {
                v[2 * j]     = make_float4(-INFINITY, -INFINITY, -INFINITY, -INFINITY);
                v[2 * j + 1] = make_float4(-INFINITY, -INFINITY, -INFINITY, -INFINITY);
                q[j]         = make_uint2(0u, 0u);   // e4m3 0x00 == 0.0
            }
        }

        // ---- extract x_t (uniform shuffle) from raw logits ----
        const int f    = t >> 2;
        const int i4t  = f >> 1;
        const int reg  = ((i4t >> 5) << 1) | (f & 1);
        const int srcl = i4t & 31;
        const int comp = t & 3;
        float4 vt;
        switch (reg) {
            case 0: vt = v[0]; break; case 1: vt = v[1]; break;
            case 2: vt = v[2]; break; case 3: vt = v[3]; break;
            case 4: vt = v[4]; break; case 5: vt = v[5]; break;
            case 6: vt = v[6]; break; default: vt = v[7]; break;
        }
        float cand = (comp == 0) ? vt.x : (comp == 1) ? vt.y : (comp == 2) ? vt.z : vt.w;
        const float x_t = __shfl_sync(0xffffffffu, cand, srcl);

        // ---- exp + sum + dot (fp8 decode) ----
        float s = 0.0f, d = 0.0f;
#pragma unroll
        for (int j = 0; j < 4; j++) {
            float4 a = v[2 * j];
            float4 b = v[2 * j + 1];
            a.x = __expf(a.x); a.y = __expf(a.y); a.z = __expf(a.z); a.w = __expf(a.w);
            b.x = __expf(b.x); b.y = __expf(b.y); b.z = __expf(b.z); b.w = __expf(b.w);
            s += (a.x + a.y + a.z + a.w) + (b.x + b.y + b.z + b.w);
            float2 p0 = f8x2_to_f2(q[j].x & 0xFFFFu);
            float2 p1 = f8x2_to_f2(q[j].x >> 16);
            float2 p2 = f8x2_to_f2(q[j].y & 0xFFFFu);
            float2 p3 = f8x2_to_f2(q[j].y >> 16);
            d += a.x * p0.x + a.y * p0.y + a.z * p1.x + a.w * p1.y
               + b.x * p2.x + b.y * p2.y + b.z * p3.x + b.w * p3.y;
        }

#pragma unroll
        for (int o = 16; o > 0; o >>= 1) {
            s += __shfl_xor_sync(0xffffffffu, s, o);
            d += __shfl_xor_sync(0xffffffffu, d, o);
        }

        if (lane == 0) {
            float lse  = __logf(s);
            float ce   = lse - x_t;                       // -log_softmax[t]
            float pro1 = __expf(x_t) / s;                 // p[t]
            float pro2 = (d * TT_INV_SCALE) / s;          // dot(p, Tt[t])
            float beta = pro1 / (pro2 + EPS_V);
            acc += beta * ce;
        }
    }

    if (lane == 0) wsum[warp] = acc;
    __syncthreads();

    if (threadIdx.x == 0) {
        float s = 0.0f;
#pragma unroll
        for (int w = 0; w < WARPS_PER_BLOCK; w++) s += wsum[w];
        g_partials[blockIdx.x] = s;
    }
}

// ---------------------------------------------------------------------------
// Kernel 3: final reduction (1024 threads, MLP-16, fixed deterministic order).
// ---------------------------------------------------------------------------
__global__ __launch_bounds__(1024) void final_reduce_kernel(float* __restrict__ out,
                                                            float invB) {
    __shared__ float sh[1024];
    const int tid = threadIdx.x;
    float acc[MAX_PARTIALS / 1024];
#pragma unroll
    for (int k = 0; k < MAX_PARTIALS / 1024; k++)
        acc[k] = g_partials[tid + 1024 * k];
    float s = 0.0f;
#pragma unroll
    for (int k = 0; k < MAX_PARTIALS / 1024; k++) s += acc[k];
    sh[tid] = s;
    __syncthreads();
#pragma unroll
    for (int o = 512; o > 0; o >>= 1) {
        if (tid < o) sh[tid] += sh[tid + o];
        __syncthreads();
    }
    if (tid == 0) out[0] = sh[0] * invB;
}

// ---------------------------------------------------------------------------
extern "C" void kernel_launch(void* const* d_in, const int* in_sizes, int n_in,
                              void* d_out, int out_size) {
    const float* logits = (const float*)d_in[0];   // [B, C] fp32
    const float* corr   = (const float*)d_in[1];   // [C, C] fp32
    const int*   target = (const int*)d_in[2];     // [B] int32
    const float* T      = (const float*)d_in[3];   // [C, C] fp32

    const int B = in_sizes[2];

    prep_T_kernel<<<C_DIM / 4, 256>>>(T, corr);    // 250 blocks, contiguous reads

    row_loss_kernel<<<LOSS_BLOCKS, 32 * WARPS_PER_BLOCK>>>(logits, target, B);

    final_reduce_kernel<<<1, 1024>>>((float*)d_out, 1.0f / (float)B);
}